// round 1
// baseline (speedup 1.0000x reference)
#include <cuda_runtime.h>
#include <math.h>
#include <stdint.h>

#define SEQ   512
#define BATCH 64
#define NIN   1024
#define NHID  1024
#define G4    4096   // 4*NHID

// ---------------------------------------------------------------------------
// Scratch (device globals; no allocation allowed in kernel_launch)
// ---------------------------------------------------------------------------
__device__ float g_xw[(size_t)SEQ * BATCH * G4];     // 512 MB : x@w_x^T + bias
__device__ float g_hs[(size_t)SEQ * BATCH * NHID];   // 128 MB : h_1..h_512
__device__ float g_c [(size_t)BATCH * NHID];         // carried cell state

// ---------------------------------------------------------------------------
// GEMM: C[M,N] = A[M,K] @ B[N,K]^T (+ bias[N] if bias != nullptr)
// 128x128 block tile, BK=8, 256 threads, 8x8 per thread. All dims divisible.
// ---------------------------------------------------------------------------
__global__ void __launch_bounds__(256) gemm_nt_bias(
    const float* __restrict__ A,
    const float* __restrict__ B,
    const float* __restrict__ bias,
    float* __restrict__ C,
    int M, int N, int K)
{
    __shared__ float As[8][128];
    __shared__ float Bs[8][128];

    const int tid  = threadIdx.x;
    const int row0 = blockIdx.y * 128;
    const int col0 = blockIdx.x * 128;

    const int lr = tid >> 1;          // 0..127 (row within tile to load)
    const int lc = (tid & 1) << 2;    // 0 or 4 (k offset, float4)

    const int tx = tid & 15;          // output col group
    const int ty = tid >> 4;          // output row group

    float acc[8][8];
#pragma unroll
    for (int i = 0; i < 8; i++)
#pragma unroll
        for (int j = 0; j < 8; j++) acc[i][j] = 0.f;

    const float* Ab = A + (size_t)row0 * K;
    const float* Bb = B + (size_t)col0 * K;

    for (int k0 = 0; k0 < K; k0 += 8) {
        float4 a4 = *(const float4*)(Ab + (size_t)lr * K + k0 + lc);
        float4 b4 = *(const float4*)(Bb + (size_t)lr * K + k0 + lc);
        __syncthreads();
        As[lc + 0][lr] = a4.x; As[lc + 1][lr] = a4.y;
        As[lc + 2][lr] = a4.z; As[lc + 3][lr] = a4.w;
        Bs[lc + 0][lr] = b4.x; Bs[lc + 1][lr] = b4.y;
        Bs[lc + 2][lr] = b4.z; Bs[lc + 3][lr] = b4.w;
        __syncthreads();
#pragma unroll
        for (int k = 0; k < 8; k++) {
            float ra[8], rb[8];
            *(float4*)&ra[0] = *(const float4*)&As[k][ty * 8];
            *(float4*)&ra[4] = *(const float4*)&As[k][ty * 8 + 4];
            *(float4*)&rb[0] = *(const float4*)&Bs[k][tx * 8];
            *(float4*)&rb[4] = *(const float4*)&Bs[k][tx * 8 + 4];
#pragma unroll
            for (int i = 0; i < 8; i++)
#pragma unroll
                for (int j = 0; j < 8; j++)
                    acc[i][j] += ra[i] * rb[j];
        }
    }

#pragma unroll
    for (int i = 0; i < 8; i++) {
        const int r = row0 + ty * 8 + i;
#pragma unroll
        for (int j = 0; j < 8; j += 4) {
            const int c = col0 + tx * 8 + j;
            float4 v;
            v.x = acc[i][j + 0]; v.y = acc[i][j + 1];
            v.z = acc[i][j + 2]; v.w = acc[i][j + 3];
            if (bias) {
                v.x += bias[c + 0]; v.y += bias[c + 1];
                v.z += bias[c + 2]; v.w += bias[c + 3];
            }
            *(float4*)(C + (size_t)r * N + c) = v;
        }
    }
}

// ---------------------------------------------------------------------------
// One LSTM timestep (fused: a = xw_t + h@w_h^T, gates, c/h update).
// Grid: 128 blocks (8 hidden units each), 256 threads.
// Thread (bg, jl): batches {2*bg, 2*bg+1}, unit j0+jl, all 4 gates.
// Inner loop per k: LDS.64 (h pair) + LDS.128 (4 gate weights) + 8 FMA.
// ---------------------------------------------------------------------------
__global__ void __launch_bounds__(256) lstm_step(
    const float* __restrict__ xw_t,   // [BATCH][G4]
    const float* __restrict__ h_in,   // [BATCH][NHID]
    const float* __restrict__ c_in,   // [BATCH][NHID]
    const float* __restrict__ w_h,    // [G4][NHID]
    float* __restrict__ h_out,        // [BATCH][NHID]
    float* __restrict__ c_out)        // [BATCH][NHID]
{
    const int JT = 8;
    const int KT = 64;
    __shared__ float hs[KT][BATCH];   // [k][b]      16 KB
    __shared__ float ws[KT][JT * 4];  // [k][j*4+g]   8 KB

    const int tid = threadIdx.x;
    const int j0  = blockIdx.x * JT;
    const int bg  = tid >> 3;         // 0..31
    const int jl  = tid & 7;          // 0..7
    const int b0  = bg * 2;

    float acc[2][4];
#pragma unroll
    for (int g = 0; g < 4; g++) {
        acc[0][g] = xw_t[(size_t)(b0    ) * G4 + g * NHID + j0 + jl];
        acc[1][g] = xw_t[(size_t)(b0 + 1) * G4 + g * NHID + j0 + jl];
    }

    for (int k0 = 0; k0 < NHID; k0 += KT) {
        __syncthreads();
        // h tile: 1024 float4 slots; lanes vary b -> conflict-free STS
#pragma unroll
        for (int q = 0; q < 4; q++) {
            const int s  = tid + 256 * q;
            const int b  = s & 63;
            const int k4 = s >> 6;           // 0..15
            float4 v = *(const float4*)(h_in + (size_t)b * NHID + k0 + k4 * 4);
            hs[k4 * 4 + 0][b] = v.x; hs[k4 * 4 + 1][b] = v.y;
            hs[k4 * 4 + 2][b] = v.z; hs[k4 * 4 + 3][b] = v.w;
        }
        // w tile: 32 rows (j,g) x 16 float4; lanes vary row -> conflict-free STS
#pragma unroll
        for (int q = 0; q < 2; q++) {
            const int s  = tid + 256 * q;
            const int rr = s & 31;           // jj*4+g
            const int k4 = s >> 5;           // 0..15
            const int jj = rr >> 2;
            const int g  = rr & 3;
            float4 v = *(const float4*)(w_h + (size_t)(g * NHID + j0 + jj) * NHID
                                             + k0 + k4 * 4);
            ws[k4 * 4 + 0][rr] = v.x; ws[k4 * 4 + 1][rr] = v.y;
            ws[k4 * 4 + 2][rr] = v.z; ws[k4 * 4 + 3][rr] = v.w;
        }
        __syncthreads();
#pragma unroll
        for (int k = 0; k < KT; k++) {
            const float2 hv = *(const float2*)&hs[k][b0];
            const float4 wv = *(const float4*)&ws[k][jl * 4];
            acc[0][0] += hv.x * wv.x; acc[0][1] += hv.x * wv.y;
            acc[0][2] += hv.x * wv.z; acc[0][3] += hv.x * wv.w;
            acc[1][0] += hv.y * wv.x; acc[1][1] += hv.y * wv.y;
            acc[1][2] += hv.y * wv.z; acc[1][3] += hv.y * wv.w;
        }
    }

    const int j = j0 + jl;
#pragma unroll
    for (int bb = 0; bb < 2; bb++) {
        const int b = b0 + bb;
        const float i_ = 1.f / (1.f + expf(-acc[bb][0]));
        const float f_ = 1.f / (1.f + expf(-acc[bb][1]));
        const float o_ = 1.f / (1.f + expf(-acc[bb][2]));
        const float gg = tanhf(acc[bb][3]);
        const float cp = c_in[(size_t)b * NHID + j];
        const float cn = f_ * cp + i_ * gg;
        c_out[(size_t)b * NHID + j] = cn;
        h_out[(size_t)b * NHID + j] = o_ * tanhf(cn);
    }
}

// ---------------------------------------------------------------------------
// Write final h and c into the output tail.
// ---------------------------------------------------------------------------
__global__ void copy_tail(float* __restrict__ out_h, float* __restrict__ out_c)
{
    const int i = blockIdx.x * blockDim.x + threadIdx.x;
    if (i < BATCH * NHID) {
        out_h[i] = g_hs[(size_t)(SEQ - 1) * BATCH * NHID + i];
        out_c[i] = g_c[i];
    }
}

// ---------------------------------------------------------------------------
// kernel_launch: graph-capturable, allocation-free.
// Inputs: x, h, c, w_x, w_h, bias, w_o. Output: [pred(512*64*1024) | h | c].
// ---------------------------------------------------------------------------
extern "C" void kernel_launch(void* const* d_in, const int* in_sizes, int n_in,
                              void* d_out, int out_size)
{
    const float* x    = (const float*)d_in[0];
    const float* h0   = (const float*)d_in[1];
    const float* c0   = (const float*)d_in[2];
    const float* w_x  = (const float*)d_in[3];
    const float* w_h  = (const float*)d_in[4];
    const float* bias = (const float*)d_in[5];
    const float* w_o  = (const float*)d_in[6];
    float* out = (float*)d_out;

    float *xw, *hs, *cbuf;
    cudaGetSymbolAddress((void**)&xw,   g_xw);
    cudaGetSymbolAddress((void**)&hs,   g_hs);
    cudaGetSymbolAddress((void**)&cbuf, g_c);

    // Phase 1: xw = x @ w_x^T + bias   [32768 x 4096]
    {
        dim3 grid(G4 / 128, (SEQ * BATCH) / 128);
        gemm_nt_bias<<<grid, 256>>>(x, w_x, bias, xw, SEQ * BATCH, G4, NIN);
    }

    // Phase 2: sequential recurrence (512 graph nodes)
    for (int t = 0; t < SEQ; t++) {
        const float* h_in = (t == 0) ? h0 : hs + (size_t)(t - 1) * BATCH * NHID;
        const float* c_in = (t == 0) ? c0 : cbuf;
        lstm_step<<<NHID / 8, 256>>>(xw + (size_t)t * BATCH * G4,
                                     h_in, c_in, w_h,
                                     hs + (size_t)t * BATCH * NHID, cbuf);
    }

    // Phase 3: pred = H @ w_o^T   [32768 x 1024]
    {
        dim3 grid(NHID / 128, (SEQ * BATCH) / 128);
        gemm_nt_bias<<<grid, 256>>>(hs, w_o, nullptr, out, SEQ * BATCH, NHID, NHID);
    }

    // Tail: final h, c
    copy_tail<<<(BATCH * NHID + 255) / 256, 256>>>(
        out + (size_t)SEQ * BATCH * NHID,
        out + (size_t)SEQ * BATCH * NHID + BATCH * NHID);
}

// round 2
// speedup vs baseline: 1.0529x; 1.0529x over previous
#include <cuda_runtime.h>
#include <math.h>
#include <stdint.h>

#define SEQ   512
#define BATCH 64
#define NIN   1024
#define NHID  1024
#define G4    4096   // 4*NHID

// ---------------------------------------------------------------------------
// Scratch (device globals; no allocation allowed in kernel_launch)
// ---------------------------------------------------------------------------
__device__ float g_xw[(size_t)SEQ * BATCH * G4];     // 512 MB : x@w_x^T + bias
__device__ float g_hs[(size_t)SEQ * BATCH * NHID];   // 128 MB : h_1..h_512
__device__ float g_c [(size_t)BATCH * NHID];         // carried cell state

// ---------------------------------------------------------------------------
// f32x2 packed helpers (Blackwell sm_100a)
// ---------------------------------------------------------------------------
__device__ __forceinline__ unsigned long long pk2(float x) {
    unsigned long long r;
    asm("mov.b64 %0, {%1, %1};" : "=l"(r) : "f"(x));
    return r;
}
__device__ __forceinline__ unsigned long long pk2b(float lo, float hi) {
    unsigned long long r;
    asm("mov.b64 %0, {%1, %2};" : "=l"(r) : "f"(lo), "f"(hi));
    return r;
}
__device__ __forceinline__ void upk2(unsigned long long v, float& lo, float& hi) {
    asm("mov.b64 {%0, %1}, %2;" : "=f"(lo), "=f"(hi) : "l"(v));
}
__device__ __forceinline__ void ffma2(unsigned long long& d,
                                      unsigned long long a,
                                      unsigned long long b) {
    asm("fma.rn.f32x2 %0, %1, %2, %0;" : "+l"(d) : "l"(a), "l"(b));
}

// ---------------------------------------------------------------------------
// GEMM: C[M,N] = A[M,K] @ B[N,K]^T (+ bias[N] if bias != nullptr)
// 128x128 tile, BK=8, 256 threads, 8x8 per thread, double-buffered smem,
// f32x2 packed FMA.
// ---------------------------------------------------------------------------
__global__ void __launch_bounds__(256) gemm_nt_bias(
    const float* __restrict__ A,
    const float* __restrict__ B,
    const float* __restrict__ bias,
    float* __restrict__ C,
    int M, int N, int K)
{
    __shared__ float As[2][8][128];
    __shared__ float Bs[2][8][128];

    const int tid  = threadIdx.x;
    const int row0 = blockIdx.y * 128;
    const int col0 = blockIdx.x * 128;

    const int lr = tid >> 1;          // 0..127 (row within tile to load)
    const int lc = (tid & 1) << 2;    // 0 or 4 (k offset, float4)

    const int tx = tid & 15;          // output col group
    const int ty = tid >> 4;          // output row group

    unsigned long long acc2[8][4];
#pragma unroll
    for (int i = 0; i < 8; i++)
#pragma unroll
        for (int j = 0; j < 4; j++) acc2[i][j] = 0ull;

    const float* Ab = A + (size_t)row0 * K;
    const float* Bb = B + (size_t)col0 * K;

    const int nT = K / 8;

    // prologue: load tile 0, store buf 0
    float4 a4 = *(const float4*)(Ab + (size_t)lr * K + lc);
    float4 b4 = *(const float4*)(Bb + (size_t)lr * K + lc);
    As[0][lc + 0][lr] = a4.x; As[0][lc + 1][lr] = a4.y;
    As[0][lc + 2][lr] = a4.z; As[0][lc + 3][lr] = a4.w;
    Bs[0][lc + 0][lr] = b4.x; Bs[0][lc + 1][lr] = b4.y;
    Bs[0][lc + 2][lr] = b4.z; Bs[0][lc + 3][lr] = b4.w;
    __syncthreads();

    for (int kt = 0; kt < nT; kt++) {
        const int cur = kt & 1;
        if (kt + 1 < nT) {
            const int k0 = (kt + 1) * 8;
            a4 = *(const float4*)(Ab + (size_t)lr * K + k0 + lc);
            b4 = *(const float4*)(Bb + (size_t)lr * K + k0 + lc);
        }
#pragma unroll
        for (int k = 0; k < 8; k++) {
            float ra[8];
            *(float4*)&ra[0] = *(const float4*)&As[cur][k][ty * 8];
            *(float4*)&ra[4] = *(const float4*)&As[cur][k][ty * 8 + 4];
            ulonglong2 rb0 = *(const ulonglong2*)&Bs[cur][k][tx * 8];
            ulonglong2 rb1 = *(const ulonglong2*)&Bs[cur][k][tx * 8 + 4];
#pragma unroll
            for (int i = 0; i < 8; i++) {
                const unsigned long long pa = pk2(ra[i]);
                ffma2(acc2[i][0], pa, rb0.x);
                ffma2(acc2[i][1], pa, rb0.y);
                ffma2(acc2[i][2], pa, rb1.x);
                ffma2(acc2[i][3], pa, rb1.y);
            }
        }
        if (kt + 1 < nT) {
            const int nxt = cur ^ 1;
            As[nxt][lc + 0][lr] = a4.x; As[nxt][lc + 1][lr] = a4.y;
            As[nxt][lc + 2][lr] = a4.z; As[nxt][lc + 3][lr] = a4.w;
            Bs[nxt][lc + 0][lr] = b4.x; Bs[nxt][lc + 1][lr] = b4.y;
            Bs[nxt][lc + 2][lr] = b4.z; Bs[nxt][lc + 3][lr] = b4.w;
            __syncthreads();
        }
    }

#pragma unroll
    for (int i = 0; i < 8; i++) {
        const int r = row0 + ty * 8 + i;
        float av[8];
#pragma unroll
        for (int j = 0; j < 4; j++) upk2(acc2[i][j], av[2 * j], av[2 * j + 1]);
#pragma unroll
        for (int j = 0; j < 8; j += 4) {
            const int c = col0 + tx * 8 + j;
            float4 v;
            v.x = av[j + 0]; v.y = av[j + 1];
            v.z = av[j + 2]; v.w = av[j + 3];
            if (bias) {
                v.x += bias[c + 0]; v.y += bias[c + 1];
                v.z += bias[c + 2]; v.w += bias[c + 3];
            }
            *(float4*)(C + (size_t)r * N + c) = v;
        }
    }
}

// ---------------------------------------------------------------------------
// One LSTM timestep (fused: a = xw_t + h@w_h^T, gates, c/h update).
// Grid: 128 blocks (8 hidden units each), 256 threads.
// Thread (bg, jl): batches {2*bg, 2*bg+1}, unit j0+jl, all 4 gates.
// Accumulators packed over gate pairs (f32x2). Double-buffered smem.
// Inner loop per k: LDS.64 (h pair) + LDS.128 (w quad) + 2 pack + 4 FFMA2.
// ---------------------------------------------------------------------------
__global__ void __launch_bounds__(256) lstm_step(
    const float* __restrict__ xw_t,   // [BATCH][G4]
    const float* __restrict__ h_in,   // [BATCH][NHID]
    const float* __restrict__ c_in,   // [BATCH][NHID]
    const float* __restrict__ w_h,    // [G4][NHID]
    float* __restrict__ h_out,        // [BATCH][NHID]
    float* __restrict__ c_out)        // [BATCH][NHID]
{
    const int KT = 64;
    __shared__ float hs[2][KT][BATCH];   // [buf][k][b]       32 KB
    __shared__ float ws[2][KT][32];      // [buf][k][jl*4+g]  16 KB

    const int tid = threadIdx.x;
    const int j0  = blockIdx.x * 8;
    const int bg  = tid >> 3;         // 0..31
    const int jl  = tid & 7;          // 0..7
    const int b0  = bg * 2;
    const int j   = j0 + jl;

    // prefetch cell state early
    const float cp0 = c_in[(size_t)(b0    ) * NHID + j];
    const float cp1 = c_in[(size_t)(b0 + 1) * NHID + j];

    // acc2[b][p]: lanes = gates (2p, 2p+1) for batch b0+b
    unsigned long long acc2[2][2];
#pragma unroll
    for (int bb = 0; bb < 2; bb++) {
        const size_t base = (size_t)(b0 + bb) * G4 + j;
        acc2[bb][0] = pk2b(xw_t[base + 0 * NHID], xw_t[base + 1 * NHID]);
        acc2[bb][1] = pk2b(xw_t[base + 2 * NHID], xw_t[base + 3 * NHID]);
    }

    // staging register loads for a K-tile
    float4 hstage[4], wstage[2];
    int hb[4], hk[4], wr[2], wk[2];
#pragma unroll
    for (int q = 0; q < 4; q++) {
        const int s = tid + 256 * q;
        hb[q] = s & 63;
        hk[q] = s >> 6;               // 0..15 (float4 index along k)
    }
#pragma unroll
    for (int q = 0; q < 2; q++) {
        const int s = tid + 256 * q;
        wr[q] = s & 31;               // jj*4+g
        wk[q] = s >> 5;               // 0..15
    }

    // prologue: load tile 0, store buf 0
#pragma unroll
    for (int q = 0; q < 4; q++)
        hstage[q] = *(const float4*)(h_in + (size_t)hb[q] * NHID + hk[q] * 4);
#pragma unroll
    for (int q = 0; q < 2; q++) {
        const int jj = wr[q] >> 2, g = wr[q] & 3;
        wstage[q] = *(const float4*)(w_h + (size_t)(g * NHID + j0 + jj) * NHID
                                          + wk[q] * 4);
    }
#pragma unroll
    for (int q = 0; q < 4; q++) {
        hs[0][hk[q] * 4 + 0][hb[q]] = hstage[q].x;
        hs[0][hk[q] * 4 + 1][hb[q]] = hstage[q].y;
        hs[0][hk[q] * 4 + 2][hb[q]] = hstage[q].z;
        hs[0][hk[q] * 4 + 3][hb[q]] = hstage[q].w;
    }
#pragma unroll
    for (int q = 0; q < 2; q++) {
        ws[0][wk[q] * 4 + 0][wr[q]] = wstage[q].x;
        ws[0][wk[q] * 4 + 1][wr[q]] = wstage[q].y;
        ws[0][wk[q] * 4 + 2][wr[q]] = wstage[q].z;
        ws[0][wk[q] * 4 + 3][wr[q]] = wstage[q].w;
    }
    __syncthreads();

    const int nT = NHID / KT;   // 16
    for (int kt = 0; kt < nT; kt++) {
        const int cur = kt & 1;
        if (kt + 1 < nT) {
            const int k0 = (kt + 1) * KT;
#pragma unroll
            for (int q = 0; q < 4; q++)
                hstage[q] = *(const float4*)(h_in + (size_t)hb[q] * NHID
                                                  + k0 + hk[q] * 4);
#pragma unroll
            for (int q = 0; q < 2; q++) {
                const int jj = wr[q] >> 2, g = wr[q] & 3;
                wstage[q] = *(const float4*)(w_h
                              + (size_t)(g * NHID + j0 + jj) * NHID
                              + k0 + wk[q] * 4);
            }
        }
#pragma unroll
        for (int k = 0; k < KT; k++) {
            const float2 hv = *(const float2*)&hs[cur][k][b0];
            const ulonglong2 wv = *(const ulonglong2*)&ws[cur][k][jl * 4];
            const unsigned long long hx = pk2(hv.x);
            const unsigned long long hy = pk2(hv.y);
            ffma2(acc2[0][0], hx, wv.x);
            ffma2(acc2[0][1], hx, wv.y);
            ffma2(acc2[1][0], hy, wv.x);
            ffma2(acc2[1][1], hy, wv.y);
        }
        if (kt + 1 < nT) {
            const int nxt = cur ^ 1;
#pragma unroll
            for (int q = 0; q < 4; q++) {
                hs[nxt][hk[q] * 4 + 0][hb[q]] = hstage[q].x;
                hs[nxt][hk[q] * 4 + 1][hb[q]] = hstage[q].y;
                hs[nxt][hk[q] * 4 + 2][hb[q]] = hstage[q].z;
                hs[nxt][hk[q] * 4 + 3][hb[q]] = hstage[q].w;
            }
#pragma unroll
            for (int q = 0; q < 2; q++) {
                ws[nxt][wk[q] * 4 + 0][wr[q]] = wstage[q].x;
                ws[nxt][wk[q] * 4 + 1][wr[q]] = wstage[q].y;
                ws[nxt][wk[q] * 4 + 2][wr[q]] = wstage[q].z;
                ws[nxt][wk[q] * 4 + 3][wr[q]] = wstage[q].w;
            }
            __syncthreads();
        }
    }

    // epilogue: gates + state update
    const float cps[2] = {cp0, cp1};
#pragma unroll
    for (int bb = 0; bb < 2; bb++) {
        float a_i, a_f, a_o, a_g;
        upk2(acc2[bb][0], a_i, a_f);
        upk2(acc2[bb][1], a_o, a_g);
        const float i_ = 1.f / (1.f + expf(-a_i));
        const float f_ = 1.f / (1.f + expf(-a_f));
        const float o_ = 1.f / (1.f + expf(-a_o));
        const float gg = tanhf(a_g);
        const float cn = f_ * cps[bb] + i_ * gg;
        const int b = b0 + bb;
        c_out[(size_t)b * NHID + j] = cn;
        h_out[(size_t)b * NHID + j] = o_ * tanhf(cn);
    }
}

// ---------------------------------------------------------------------------
// Write final h and c into the output tail.
// ---------------------------------------------------------------------------
__global__ void copy_tail(float* __restrict__ out_h, float* __restrict__ out_c)
{
    const int i = blockIdx.x * blockDim.x + threadIdx.x;
    if (i < BATCH * NHID) {
        out_h[i] = g_hs[(size_t)(SEQ - 1) * BATCH * NHID + i];
        out_c[i] = g_c[i];
    }
}

// ---------------------------------------------------------------------------
// kernel_launch: graph-capturable, allocation-free.
// Inputs: x, h, c, w_x, w_h, bias, w_o. Output: [pred(512*64*1024) | h | c].
// ---------------------------------------------------------------------------
extern "C" void kernel_launch(void* const* d_in, const int* in_sizes, int n_in,
                              void* d_out, int out_size)
{
    const float* x    = (const float*)d_in[0];
    const float* h0   = (const float*)d_in[1];
    const float* c0   = (const float*)d_in[2];
    const float* w_x  = (const float*)d_in[3];
    const float* w_h  = (const float*)d_in[4];
    const float* bias = (const float*)d_in[5];
    const float* w_o  = (const float*)d_in[6];
    float* out = (float*)d_out;

    float *xw, *hs, *cbuf;
    cudaGetSymbolAddress((void**)&xw,   g_xw);
    cudaGetSymbolAddress((void**)&hs,   g_hs);
    cudaGetSymbolAddress((void**)&cbuf, g_c);

    // Phase 1: xw = x @ w_x^T + bias   [32768 x 4096]
    {
        dim3 grid(G4 / 128, (SEQ * BATCH) / 128);
        gemm_nt_bias<<<grid, 256>>>(x, w_x, bias, xw, SEQ * BATCH, G4, NIN);
    }

    // Phase 2: sequential recurrence (512 graph nodes)
    for (int t = 0; t < SEQ; t++) {
        const float* h_in = (t == 0) ? h0 : hs + (size_t)(t - 1) * BATCH * NHID;
        const float* c_in = (t == 0) ? c0 : cbuf;
        lstm_step<<<NHID / 8, 256>>>(xw + (size_t)t * BATCH * G4,
                                     h_in, c_in, w_h,
                                     hs + (size_t)t * BATCH * NHID, cbuf);
    }

    // Phase 3: pred = H @ w_o^T   [32768 x 1024]
    {
        dim3 grid(NHID / 128, (SEQ * BATCH) / 128);
        gemm_nt_bias<<<grid, 256>>>(hs, w_o, nullptr, out, SEQ * BATCH, NHID, NHID);
    }

    // Tail: final h, c
    copy_tail<<<(BATCH * NHID + 255) / 256, 256>>>(
        out + (size_t)SEQ * BATCH * NHID,
        out + (size_t)SEQ * BATCH * NHID + BATCH * NHID);
}